// round 13
// baseline (speedup 1.0000x reference)
#include <cuda_runtime.h>
#include <cuda_fp16.h>
#include <cstdint>

#define B_   2
#define S_   2048
#define E_   1024
#define H_   16
#define D_   64
#define NTOK (B_*S_)

// ---------------- static scratch ----------------
__device__ __half g_x16 [NTOK*E_];
__device__ __half g_wh16[4*E_*E_], g_wl16[E_*E_];   // lo kept only for Wo
__device__ __half g_qkv16[3LL*NTOK*E_];  // q | k | v
__device__ __half g_ctx16[NTOK*E_];

// ---------------- asm helpers ----------------
__device__ __forceinline__ uint32_t smem_u32(const void* p) {
    uint32_t a;
    asm("{ .reg .u64 t; cvta.to.shared.u64 t, %1; cvt.u32.u64 %0, t; }" : "=r"(a) : "l"(p));
    return a;
}
__device__ __forceinline__ void cp16(uint32_t dst, const void* src) {
    asm volatile("cp.async.cg.shared.global [%0], [%1], 16;" :: "r"(dst), "l"(src));
}
__device__ __forceinline__ void cp_commit() { asm volatile("cp.async.commit_group;"); }
__device__ __forceinline__ void cp_wait2()  { asm volatile("cp.async.wait_group 2;"); }
__device__ __forceinline__ void cp_wait1()  { asm volatile("cp.async.wait_group 1;"); }
__device__ __forceinline__ void cp_wait0()  { asm volatile("cp.async.wait_group 0;"); }
__device__ __forceinline__ void ldsm4(uint32_t* r, uint32_t addr) {
    asm volatile("ldmatrix.sync.aligned.m8n8.x4.shared.b16 {%0,%1,%2,%3}, [%4];"
        : "=r"(r[0]), "=r"(r[1]), "=r"(r[2]), "=r"(r[3]) : "r"(addr));
}
__device__ __forceinline__ void ldsm4t(uint32_t* r, uint32_t addr) {
    asm volatile("ldmatrix.sync.aligned.m8n8.x4.trans.shared.b16 {%0,%1,%2,%3}, [%4];"
        : "=r"(r[0]), "=r"(r[1]), "=r"(r[2]), "=r"(r[3]) : "r"(addr));
}
__device__ __forceinline__ void mma_f16(float* d, const uint32_t* a, const uint32_t* b) {
    asm volatile("mma.sync.aligned.m16n8k16.row.col.f32.f16.f16.f32 "
        "{%0,%1,%2,%3}, {%4,%5,%6,%7}, {%8,%9}, {%0,%1,%2,%3};"
        : "+f"(d[0]), "+f"(d[1]), "+f"(d[2]), "+f"(d[3])
        : "r"(a[0]), "r"(a[1]), "r"(a[2]), "r"(a[3]), "r"(b[0]), "r"(b[1]));
}
__device__ __forceinline__ uint32_t swz16(int row, int chunk) {
    return (uint32_t)(row * 128 + ((chunk ^ (row & 7)) << 4));
}
// full-E rows (2048 B), XOR-swizzled 16B chunks
__device__ __forceinline__ uint32_t swzE(int r, int c) {
    return (uint32_t)(r * 2048 + ((c ^ (r & 7)) << 4));
}
__device__ __forceinline__ void sts64(uint32_t addr, float x, float y) {
    asm volatile("st.shared.v2.f32 [%0], {%1, %2};" :: "r"(addr), "f"(x), "f"(y));
}
__device__ __forceinline__ float lds32f(uint32_t addr) {
    float v;
    asm volatile("ld.shared.f32 %0, [%1];" : "=f"(v) : "r"(addr));
    return v;
}

// ---------------- utility kernels ----------------
__global__ void cvt16_kernel(const float* __restrict__ src, __half* __restrict__ dst, int n) {
    for (int i = blockIdx.x * 256 + threadIdx.x; i < n; i += gridDim.x * 256)
        dst[i] = __float2half(src[i]);
}

// Wq,Wk,Wv -> fp16 (hi only); Wo -> fp16 hi + lo residual
__global__ void prep_w_kernel(const float* __restrict__ w0, const float* __restrict__ w1,
                              const float* __restrict__ w2, const float* __restrict__ w3,
                              __half* __restrict__ hi, __half* __restrict__ lo) {
    const int z = blockIdx.y;
    const float* src = (z == 0) ? w0 : (z == 1) ? w1 : (z == 2) ? w2 : w3;
    const int off = z * (E_ * E_);
    for (int i = blockIdx.x * 256 + threadIdx.x; i < E_ * E_; i += gridDim.x * 256) {
        float f = src[i];
        __half h = __float2half(f);
        hi[off + i] = h;
        if (z == 3) lo[i] = __float2half(f - __half2float(h));
    }
}

// ---------------- fp16 GEMM (1- or 2-term weights), 3-stage pipeline ----------------
template <int BN, bool TWO>
__global__ __launch_bounds__(512)
void gemm_w(const __half* __restrict__ A,
            const __half* __restrict__ Bhi, const __half* __restrict__ Blo,
            const float* __restrict__ bias0, const float* __restrict__ bias1,
            const float* __restrict__ bias2,
            float* __restrict__ Cf, __half* __restrict__ C16,
            int lda, int ldb, int ldc, int K,
            long long bH, long long cH, float zscale)
{
    extern __shared__ char smem[];
    constexpr int ASZ = 128 * 80;
    constexpr int OFF_BHI = ASZ;
    constexpr int OFF_BLO = 2 * ASZ;
    constexpr int STAGE   = (TWO ? 3 : 2) * ASZ;

    const int tid  = threadIdx.x;
    const int lane = tid & 31;
    const int wid  = tid >> 5;
    const int wm   = wid & 3;
    const int wn   = wid >> 2;
    const int zh   = blockIdx.z;
    const uint32_t sb = smem_u32(smem);
    const float* bias = (zh == 1) ? bias1 : ((zh == 2) ? bias2 : bias0);
    const float csc = (zh == 0) ? zscale : 1.0f;

    const __half* pA   = A + (long long)blockIdx.y * 128 * lda;
    const __half* pBhi = Bhi + zh * bH + (long long)blockIdx.x * BN * ldb;
    const __half* pBlo = TWO ? (Blo + (long long)blockIdx.x * BN * ldb) : nullptr;

    const int r4 = tid >> 2, c4 = tid & 3;

    auto load_stage = [&](int kb, int stg) {
        uint32_t s0 = sb + stg * STAGE;
        cp16(s0 + r4 * 80 + c4 * 16, pA + (long long)r4 * lda + kb * 32 + c4 * 8);
        long long g = (long long)r4 * ldb + kb * 32 + c4 * 8;
        cp16(s0 + OFF_BHI + r4 * 80 + c4 * 16, pBhi + g);
        if (TWO) cp16(s0 + OFF_BLO + r4 * 80 + c4 * 16, pBlo + g);
    };

    const int KI = K >> 5;
    load_stage(0, 0); cp_commit();
    load_stage(1, 1); cp_commit();
    load_stage(2, 2); cp_commit();

    float acc[2][4][4] = {};

    const int a_r0 = wm * 32 + (lane & 15);
    const int a_c  = (lane >> 4) * 16;
    const int b_r  = wn * 32 + (lane & 7) + ((lane >> 4) & 1) * 8;
    const int b_c  = ((lane >> 3) & 1) * 16;

    int stg = 0;
    for (int kb = 0; kb < KI; kb++) {
        cp_wait2();
        __syncthreads();
        const uint32_t s0 = sb + stg * STAGE;
#pragma unroll
        for (int ks = 0; ks < 2; ks++) {
            const uint32_t koff = ks * 32;
            uint32_t ah[2][4], bh[2][4];
#pragma unroll
            for (int mt = 0; mt < 2; mt++)
                ldsm4(ah[mt], s0 + (a_r0 + mt * 16) * 80 + a_c + koff);
#pragma unroll
            for (int nt2 = 0; nt2 < 2; nt2++)
                ldsm4(bh[nt2], s0 + OFF_BHI + (b_r + nt2 * 16) * 80 + b_c + koff);
#pragma unroll
            for (int mt = 0; mt < 2; mt++)
#pragma unroll
                for (int nt2 = 0; nt2 < 2; nt2++) {
                    mma_f16(acc[mt][nt2 * 2],     ah[mt], bh[nt2]);
                    mma_f16(acc[mt][nt2 * 2 + 1], ah[mt], bh[nt2] + 2);
                }
            if (TWO) {
                uint32_t bl[2][4];
#pragma unroll
                for (int nt2 = 0; nt2 < 2; nt2++)
                    ldsm4(bl[nt2], s0 + OFF_BLO + (b_r + nt2 * 16) * 80 + b_c + koff);
#pragma unroll
                for (int mt = 0; mt < 2; mt++)
#pragma unroll
                    for (int nt2 = 0; nt2 < 2; nt2++) {
                        mma_f16(acc[mt][nt2 * 2],     ah[mt], bl[nt2]);
                        mma_f16(acc[mt][nt2 * 2 + 1], ah[mt], bl[nt2] + 2);
                    }
            }
        }
        __syncthreads();
        if (kb + 3 < KI) load_stage(kb + 3, stg);
        cp_commit();
        stg = (stg == 2) ? 0 : stg + 1;
    }

    const long long cb = zh * cH;
#pragma unroll
    for (int mt = 0; mt < 2; mt++) {
        const int mrow = blockIdx.y * 128 + wm * 32 + mt * 16 + (lane >> 2);
#pragma unroll
        for (int nt = 0; nt < 4; nt++) {
            const int col = blockIdx.x * BN + wn * 32 + nt * 8 + (lane & 3) * 2;
            float v0 = acc[mt][nt][0], v1 = acc[mt][nt][1];
            float v2 = acc[mt][nt][2], v3 = acc[mt][nt][3];
            if (bias) {
                float b0 = __ldg(&bias[col]), b1 = __ldg(&bias[col + 1]);
                v0 += b0; v1 += b1; v2 += b0; v3 += b1;
            }
            if (Cf) {
                *(float2*)(Cf + cb + (long long)mrow * ldc + col)       = make_float2(v0, v1);
                *(float2*)(Cf + cb + (long long)(mrow + 8) * ldc + col) = make_float2(v2, v3);
            } else {
                v0 *= csc; v1 *= csc; v2 *= csc; v3 *= csc;
                __half2 p0; p0.x = __float2half(v0); p0.y = __float2half(v1);
                __half2 p1; p1.x = __float2half(v2); p1.y = __float2half(v3);
                *(__half2*)(C16 + cb + (long long)mrow * ldc + col)       = p0;
                *(__half2*)(C16 + cb + (long long)(mrow + 8) * ldc + col) = p1;
            }
        }
    }
}

// ---------------- fused attention v3: 256 thr, 2 blocks/SM, register probs ----------------
// Block: (b, 16 queries); 8 warps, warp = 2 heads; k-tiles of 16.
// QK C-frags -> exp2 -> PV A-frags entirely in registers (FA-style repack).
// Only denominators cross warps (2-head partial planes -> inv plane).
#define AQ3 16
#define NIT3 (S_/16)                 // 128
#define KB_SZ 32768
#define OFF_VB 65536
#define OFF_PART 98304
#define PART_ROW 72
#define PART_PLANE (16*PART_ROW)     // 1152
#define OFF_INV3 (OFF_PART + 8*PART_PLANE)   // 107520
#define INV_ROW 48
#define ATT3_SMEM (OFF_INV3 + 16*INV_ROW)    // 108288

__global__ __launch_bounds__(256, 2)
void attn_fused3(const __half* __restrict__ q16, const __half* __restrict__ k16,
                 const __half* __restrict__ v16, __half* __restrict__ ctx16)
{
    extern __shared__ char smem[];
    const int tid = threadIdx.x, lane = tid & 31, wid = tid >> 5;   // 8 warps
    const int b = blockIdx.y, q0 = blockIdx.x * AQ3;
    const uint32_t sb = smem_u32(smem);
    const long long bS = (long long)b * S_;

    // ---- prologue: stage Q (16 rows x 2KB) into KBUF0, hoist A-frags
#pragma unroll
    for (int p = 0; p < 8; p++) {
        int idx = tid + p * 256, r = idx >> 7, c = idx & 127;
        cp16(sb + swzE(r, c), q16 + (bS + q0 + r) * E_ + c * 8);
    }
    cp_commit(); cp_wait0();
    __syncthreads();
    uint32_t qf[2][4][4];
#pragma unroll
    for (int hh = 0; hh < 2; hh++)
#pragma unroll
        for (int ks = 0; ks < 4; ks++) {
            int h = wid * 2 + hh;
            ldsm4(qf[hh][ks], sb + swzE(lane & 15, h * 8 + ks * 2 + (lane >> 4)));
        }
    __syncthreads();

    auto load_k = [&](int kt, int stg) {
        const uint32_t d0 = sb + stg * KB_SZ;
#pragma unroll
        for (int p = 0; p < 8; p++) {
            int idx = tid + p * 256, r = idx >> 7, c = idx & 127;
            cp16(d0 + swzE(r, c), k16 + (bS + kt * 16 + r) * E_ + c * 8);
        }
    };
    auto load_v = [&](int kt) {
#pragma unroll
        for (int p = 0; p < 8; p++) {
            int idx = tid + p * 256, r = idx >> 7, c = idx & 127;
            cp16(sb + OFF_VB + swzE(r, c), v16 + (bS + kt * 16 + r) * E_ + c * 8);
        }
    };

    load_k(0, 0); load_v(0); cp_commit();
    load_k(1, 1); cp_commit();

    float acc[2][8][4] = {};
    const int pr = lane >> 2, pc = (lane & 3) * 2;

    for (int kt = 0; kt < NIT3; kt++) {
        cp_wait1();
        __syncthreads();
        const uint32_t kbuf = sb + (kt & 1) * KB_SZ;

        // ---- phase 1: QK + exp2, keep probs as A-frags in registers
        uint32_t ph[2][4];
        float psum[8];
#pragma unroll
        for (int i = 0; i < 8; i++) psum[i] = 0.f;
#pragma unroll
        for (int hh = 0; hh < 2; hh++) {
            const int h = wid * 2 + hh;
            float sacc[2][4] = {};
#pragma unroll
            for (int ks = 0; ks < 4; ks++) {
                uint32_t bf[4];
                int row = (lane & 7) + ((lane >> 4) & 1) * 8;
                int ch  = h * 8 + ks * 2 + ((lane >> 3) & 1);
                ldsm4(bf, kbuf + swzE(row, ch));
                mma_f16(sacc[0], qf[hh][ks], bf);
                mma_f16(sacc[1], qf[hh][ks], bf + 2);
            }
#pragma unroll
            for (int j = 0; j < 2; j++) {
                float e0 = exp2f(sacc[j][0]), e1 = exp2f(sacc[j][1]);
                float e2 = exp2f(sacc[j][2]), e3 = exp2f(sacc[j][3]);
                psum[j * 4 + 0] += e0; psum[j * 4 + 1] += e1;
                psum[j * 4 + 2] += e2; psum[j * 4 + 3] += e3;
                __half2 p01 = __floats2half2_rn(e0, e1);
                __half2 p23 = __floats2half2_rn(e2, e3);
                ph[hh][j * 2]     = *(uint32_t*)&p01;   // (rows pr,   k cols j*8+pc..+1)
                ph[hh][j * 2 + 1] = *(uint32_t*)&p23;   // (rows pr+8, same cols)
            }
        }
        // store 2-head partial denominators to this warp's plane
        {
            const uint32_t pb = sb + OFF_PART + wid * PART_PLANE;
#pragma unroll
            for (int j = 0; j < 2; j++) {
                sts64(pb + pr * PART_ROW       + (j * 8 + pc) * 4, psum[j * 4 + 0], psum[j * 4 + 1]);
                sts64(pb + (pr + 8) * PART_ROW + (j * 8 + pc) * 4, psum[j * 4 + 2], psum[j * 4 + 3]);
            }
        }
        __syncthreads();

        // ---- phase 2: sum 8 planes -> inv (16q x 16k fp16)
        {
            const int q = tid >> 4, k = tid & 15;
            float s = 0.f;
#pragma unroll
            for (int w = 0; w < 8; w++)
                s += lds32f(sb + OFF_PART + w * PART_PLANE + q * PART_ROW + k * 4);
            __half iv = __float2half(1.f / s);
            asm volatile("st.shared.u16 [%0], %1;"
                :: "r"(sb + OFF_INV3 + q * INV_ROW + k * 2), "h"(*(uint16_t*)&iv));
        }
        __syncthreads();

        // ---- phase 3: PV with register probs x inv frags
        uint32_t ivf[4];
        ldsm4(ivf, sb + OFF_INV3 + (lane & 15) * INV_ROW + (lane >> 4) * 16);
        const uint32_t vbuf = sb + OFF_VB;
#pragma unroll
        for (int hh = 0; hh < 2; hh++) {
            const int h = wid * 2 + hh;
            uint32_t pf[4];
#pragma unroll
            for (int j = 0; j < 4; j++) {
                __half2 m = __hmul2(*(__half2*)&ph[hh][j], *(__half2*)&ivf[j]);
                pf[j] = *(uint32_t*)&m;
            }
#pragma unroll
            for (int nt = 0; nt < 4; nt++) {
                uint32_t bf[4];
                ldsm4t(bf, vbuf + swzE(lane & 15, h * 8 + nt * 2 + (lane >> 4)));
                mma_f16(acc[hh][nt * 2],     pf, bf);
                mma_f16(acc[hh][nt * 2 + 1], pf, bf + 2);
            }
        }
        __syncthreads();

        if (kt + 1 < NIT3) load_v(kt + 1);
        cp_commit();
        if (kt + 2 < NIT3) load_k(kt + 2, kt & 1);
        cp_commit();
    }

    // ---- epilogue: ctx[b][q][h*64+d] fp16
#pragma unroll
    for (int hh = 0; hh < 2; hh++) {
        const int h = wid * 2 + hh;
#pragma unroll
        for (int nt = 0; nt < 8; nt++) {
            const int col = h * 64 + nt * 8 + pc;
            __half2 p0; p0.x = __float2half(acc[hh][nt][0]); p0.y = __float2half(acc[hh][nt][1]);
            __half2 p1; p1.x = __float2half(acc[hh][nt][2]); p1.y = __float2half(acc[hh][nt][3]);
            *(__half2*)(ctx16 + (bS + q0 + pr) * E_ + col)     = p0;
            *(__half2*)(ctx16 + (bS + q0 + pr + 8) * E_ + col) = p1;
        }
    }
}

// ---------------- launch ----------------
extern "C" void kernel_launch(void* const* d_in, const int* in_sizes, int n_in,
                              void* d_out, int out_size)
{
    const float* x  = (const float*)d_in[0];
    const float* Wq = (const float*)d_in[1];
    const float* bq = (const float*)d_in[2];
    const float* Wk = (const float*)d_in[3];
    const float* bk = (const float*)d_in[4];
    const float* Wv = (const float*)d_in[5];
    const float* bv = (const float*)d_in[6];
    const float* Wo = (const float*)d_in[7];
    const float* bo = (const float*)d_in[8];
    float* out = (float*)d_out;

    __half *x16, *wh16, *wl16, *qkv16, *ctx16;
    cudaGetSymbolAddress((void**)&x16,  g_x16);
    cudaGetSymbolAddress((void**)&wh16, g_wh16);
    cudaGetSymbolAddress((void**)&wl16, g_wl16);
    cudaGetSymbolAddress((void**)&qkv16, g_qkv16);
    cudaGetSymbolAddress((void**)&ctx16, g_ctx16);

    constexpr int SMEM_W1 = 3 * 2 * 128 * 80;   // 61440
    constexpr int SMEM_W2 = 3 * 3 * 128 * 80;   // 92160
    cudaFuncSetAttribute(gemm_w<128, false>, cudaFuncAttributeMaxDynamicSharedMemorySize, SMEM_W1);
    cudaFuncSetAttribute(gemm_w<128, true>,  cudaFuncAttributeMaxDynamicSharedMemorySize, SMEM_W2);
    cudaFuncSetAttribute(attn_fused3, cudaFuncAttributeMaxDynamicSharedMemorySize, ATT3_SMEM);

    const int EE = E_ * E_;
    const long long QKV = (long long)NTOK * E_;
    __half* q16 = qkv16;
    __half* k16 = qkv16 + QKV;
    __half* v16 = qkv16 + 2 * QKV;
    const float SC = 0.125f * 1.4426950408889634f;

    // 1) convert inputs
    cvt16_kernel<<<2048, 256>>>(x, x16, NTOK * E_);
    prep_w_kernel<<<dim3(256, 4), 256>>>(Wq, Wk, Wv, Wo, wh16, wl16);

    // 2) q,k,v projections (1-term fp16 weights; q scaled by SC)
    gemm_w<128, false><<<dim3(E_ / 128, NTOK / 128, 3), 512, SMEM_W1>>>(
        x16, wh16, nullptr, bq, bk, bv,
        nullptr, qkv16, E_, E_, E_, E_, (long long)EE, QKV, SC);

    // 3) fused attention v3 (2 blocks/SM)
    attn_fused3<<<dim3(S_ / AQ3, B_), 256, ATT3_SMEM>>>(q16, k16, v16, ctx16);

    // 4) output projection (2-term weights) -> d_out (fp32)
    gemm_w<128, true><<<dim3(E_ / 128, NTOK / 128, 1), 512, SMEM_W2>>>(
        ctx16, wh16 + 3 * EE, wl16, bo, nullptr, nullptr,
        out, nullptr, E_, E_, E_, E_, 0, 0, 1.0f);
}

// round 14
// speedup vs baseline: 1.1098x; 1.1098x over previous
#include <cuda_runtime.h>
#include <cuda_fp16.h>
#include <cstdint>

#define B_   2
#define S_   2048
#define E_   1024
#define H_   16
#define D_   64
#define NTOK (B_*S_)

// ---------------- static scratch ----------------
__device__ __half g_x16 [NTOK*E_];
__device__ __half g_wh16[4*E_*E_];
__device__ __half g_qkv16[3LL*NTOK*E_];  // q | k | v
__device__ __half g_ctx16[NTOK*E_];

// ---------------- asm helpers ----------------
__device__ __forceinline__ uint32_t smem_u32(const void* p) {
    uint32_t a;
    asm("{ .reg .u64 t; cvta.to.shared.u64 t, %1; cvt.u32.u64 %0, t; }" : "=r"(a) : "l"(p));
    return a;
}
__device__ __forceinline__ void cp16(uint32_t dst, const void* src) {
    asm volatile("cp.async.cg.shared.global [%0], [%1], 16;" :: "r"(dst), "l"(src));
}
__device__ __forceinline__ void cp_commit() { asm volatile("cp.async.commit_group;"); }
__device__ __forceinline__ void cp_wait2()  { asm volatile("cp.async.wait_group 2;"); }
__device__ __forceinline__ void cp_wait1()  { asm volatile("cp.async.wait_group 1;"); }
__device__ __forceinline__ void cp_wait0()  { asm volatile("cp.async.wait_group 0;"); }
__device__ __forceinline__ void ldsm4(uint32_t* r, uint32_t addr) {
    asm volatile("ldmatrix.sync.aligned.m8n8.x4.shared.b16 {%0,%1,%2,%3}, [%4];"
        : "=r"(r[0]), "=r"(r[1]), "=r"(r[2]), "=r"(r[3]) : "r"(addr));
}
__device__ __forceinline__ void ldsm4t(uint32_t* r, uint32_t addr) {
    asm volatile("ldmatrix.sync.aligned.m8n8.x4.trans.shared.b16 {%0,%1,%2,%3}, [%4];"
        : "=r"(r[0]), "=r"(r[1]), "=r"(r[2]), "=r"(r[3]) : "r"(addr));
}
__device__ __forceinline__ void mma_f16(float* d, const uint32_t* a, const uint32_t* b) {
    asm volatile("mma.sync.aligned.m16n8k16.row.col.f32.f16.f16.f32 "
        "{%0,%1,%2,%3}, {%4,%5,%6,%7}, {%8,%9}, {%0,%1,%2,%3};"
        : "+f"(d[0]), "+f"(d[1]), "+f"(d[2]), "+f"(d[3])
        : "r"(a[0]), "r"(a[1]), "r"(a[2]), "r"(a[3]), "r"(b[0]), "r"(b[1]));
}
__device__ __forceinline__ uint32_t swz16(int row, int chunk) {
    return (uint32_t)(row * 128 + ((chunk ^ (row & 7)) << 4));
}

// ---------------- prep: x and all 4 weights -> fp16 in one launch ----------------
__global__ void prep_all_kernel(const float* __restrict__ x,
                                const float* __restrict__ w0, const float* __restrict__ w1,
                                const float* __restrict__ w2, const float* __restrict__ w3,
                                __half* __restrict__ x16, __half* __restrict__ wh16) {
    const int z = blockIdx.y;
    const float* src;
    __half* dst;
    int n;
    if (z == 0) { src = x;  dst = x16;              n = NTOK * E_; }
    else {
        src = (z == 1) ? w0 : (z == 2) ? w1 : (z == 3) ? w2 : w3;
        dst = wh16 + (z - 1) * (E_ * E_);
        n = E_ * E_;
    }
    for (int i = blockIdx.x * 256 + threadIdx.x; i < n; i += gridDim.x * 256)
        dst[i] = __float2half(src[i]);
}

// ---------------- 1-term fp16 GEMM, 3-stage pipeline ----------------
// C = (A @ B^T + bias) * (zh==0 ? zscale : 1); fp32 (Cf) or fp16 (C16) out.
// 512 threads, 16 warps 4m x 4n; warp tile 32x32; BM=BN=128, BK=32.
template <int BN>
__global__ __launch_bounds__(512)
void gemm_w(const __half* __restrict__ A,
            const __half* __restrict__ Bhi,
            const float* __restrict__ bias0, const float* __restrict__ bias1,
            const float* __restrict__ bias2,
            float* __restrict__ Cf, __half* __restrict__ C16,
            int lda, int ldb, int ldc, int K,
            long long bH, long long cH, float zscale)
{
    extern __shared__ char smem[];
    constexpr int ASZ = 128 * 80;
    constexpr int OFF_B = ASZ;
    constexpr int STAGE = 2 * ASZ;       // 20480; 3 stages = 61440

    const int tid  = threadIdx.x;
    const int lane = tid & 31;
    const int wid  = tid >> 5;
    const int wm   = wid & 3;
    const int wn   = wid >> 2;
    const int zh   = blockIdx.z;
    const uint32_t sb = smem_u32(smem);
    const float* bias = (zh == 1) ? bias1 : ((zh == 2) ? bias2 : bias0);
    const float csc = (zh == 0) ? zscale : 1.0f;

    const __half* pA = A + (long long)blockIdx.y * 128 * lda;
    const __half* pB = Bhi + zh * bH + (long long)blockIdx.x * BN * ldb;

    const int r4 = tid >> 2, c4 = tid & 3;

    auto load_stage = [&](int kb, int stg) {
        uint32_t s0 = sb + stg * STAGE;
        cp16(s0 + r4 * 80 + c4 * 16, pA + (long long)r4 * lda + kb * 32 + c4 * 8);
        cp16(s0 + OFF_B + r4 * 80 + c4 * 16, pB + (long long)r4 * ldb + kb * 32 + c4 * 8);
    };

    const int KI = K >> 5;
    load_stage(0, 0); cp_commit();
    load_stage(1, 1); cp_commit();
    load_stage(2, 2); cp_commit();

    float acc[2][4][4] = {};

    const int a_r0 = wm * 32 + (lane & 15);
    const int a_c  = (lane >> 4) * 16;
    const int b_r  = wn * 32 + (lane & 7) + ((lane >> 4) & 1) * 8;
    const int b_c  = ((lane >> 3) & 1) * 16;

    int stg = 0;
    for (int kb = 0; kb < KI; kb++) {
        cp_wait2();
        __syncthreads();
        const uint32_t s0 = sb + stg * STAGE;
#pragma unroll
        for (int ks = 0; ks < 2; ks++) {
            const uint32_t koff = ks * 32;
            uint32_t ah[2][4], bh[2][4];
#pragma unroll
            for (int mt = 0; mt < 2; mt++)
                ldsm4(ah[mt], s0 + (a_r0 + mt * 16) * 80 + a_c + koff);
#pragma unroll
            for (int nt2 = 0; nt2 < 2; nt2++)
                ldsm4(bh[nt2], s0 + OFF_B + (b_r + nt2 * 16) * 80 + b_c + koff);
#pragma unroll
            for (int mt = 0; mt < 2; mt++)
#pragma unroll
                for (int nt2 = 0; nt2 < 2; nt2++) {
                    mma_f16(acc[mt][nt2 * 2],     ah[mt], bh[nt2]);
                    mma_f16(acc[mt][nt2 * 2 + 1], ah[mt], bh[nt2] + 2);
                }
        }
        __syncthreads();
        if (kb + 3 < KI) load_stage(kb + 3, stg);
        cp_commit();
        stg = (stg == 2) ? 0 : stg + 1;
    }

    const long long cb = zh * cH;
#pragma unroll
    for (int mt = 0; mt < 2; mt++) {
        const int mrow = blockIdx.y * 128 + wm * 32 + mt * 16 + (lane >> 2);
#pragma unroll
        for (int nt = 0; nt < 4; nt++) {
            const int col = blockIdx.x * BN + wn * 32 + nt * 8 + (lane & 3) * 2;
            float v0 = acc[mt][nt][0], v1 = acc[mt][nt][1];
            float v2 = acc[mt][nt][2], v3 = acc[mt][nt][3];
            if (bias) {
                float b0 = __ldg(&bias[col]), b1 = __ldg(&bias[col + 1]);
                v0 += b0; v1 += b1; v2 += b0; v3 += b1;
            }
            if (Cf) {
                *(float2*)(Cf + cb + (long long)mrow * ldc + col)       = make_float2(v0, v1);
                *(float2*)(Cf + cb + (long long)(mrow + 8) * ldc + col) = make_float2(v2, v3);
            } else {
                v0 *= csc; v1 *= csc; v2 *= csc; v3 *= csc;
                __half2 p0; p0.x = __float2half(v0); p0.y = __float2half(v1);
                __half2 p1; p1.x = __float2half(v2); p1.y = __float2half(v3);
                *(__half2*)(C16 + cb + (long long)mrow * ldc + col)       = p0;
                *(__half2*)(C16 + cb + (long long)(mrow + 8) * ldc + col) = p1;
            }
        }
    }
}

// ---------------- fully fused attention (round-12 validated version) ----------------
#define AQ 32
#define NIT (S_/32)                 // 64
#define OFF_K1  65536
#define OFF_V   131072
#define OFF_P   196608
#define OFF_INV 229376
#define ATT_SMEM 231936

__global__ __launch_bounds__(512, 1)
void attn_fused(const __half* __restrict__ q16, const __half* __restrict__ k16,
                const __half* __restrict__ v16, __half* __restrict__ ctx16)
{
    extern __shared__ char smem[];
    const int tid = threadIdx.x, lane = tid & 31, wid = tid >> 5;  // wid = head
    const int b = blockIdx.y, q0 = blockIdx.x * AQ;
    const uint32_t sb = smem_u32(smem);

    // ---- prologue: stage Q, hoist fragments (q already scaled by log2e/8)
#pragma unroll
    for (int p = 0; p < 8; p++) {
        int idx = tid + p * 512, r = idx >> 3, c = idx & 7;
        long long g = ((long long)(b * S_ + q0 + (r & 31))) * E_ + (r >> 5) * 64 + c * 8;
        cp16(sb + swz16(r, c), q16 + g);
    }
    cp_commit(); cp_wait0();
    __syncthreads();
    uint32_t qf[2][4][4];
#pragma unroll
    for (int mt = 0; mt < 2; mt++)
#pragma unroll
        for (int ks = 0; ks < 4; ks++) {
            int row = wid * 32 + mt * 16 + (lane & 15);
            ldsm4(qf[mt][ks], sb + swz16(row, ks * 2 + (lane >> 4)));
        }
    __syncthreads();

    auto load_k = [&](int kt, int stg) {
        const uint32_t d0 = sb + stg * OFF_K1;
#pragma unroll
        for (int p = 0; p < 8; p++) {
            int idx = tid + p * 512, r = idx >> 3, c = idx & 7;
            long long g = ((long long)(b * S_ + kt * 32 + (r & 31))) * E_ + (r >> 5) * 64 + c * 8;
            cp16(d0 + swz16(r, c), k16 + g);
        }
    };
    auto load_v = [&](int kt) {
        const uint32_t d0 = sb + OFF_V;
#pragma unroll
        for (int p = 0; p < 8; p++) {
            int idx = tid + p * 512, r = idx >> 3, c = idx & 7;
            long long g = ((long long)(b * S_ + kt * 32 + (r & 31))) * E_ + (r >> 5) * 64 + c * 8;
            cp16(d0 + swz16(r, c), v16 + g);
        }
    };

    load_k(0, 0); load_v(0); cp_commit();
    load_k(1, 1); cp_commit();

    float acc[2][8][4] = {};
    const int pq = tid >> 4, pk = (tid & 15) * 2;

    for (int kt = 0; kt < NIT; kt++) {
        cp_wait1();
        __syncthreads();
        const int stg = kt & 1;
        const uint32_t kslice = sb + stg * OFF_K1 + wid * 32 * 128;
        const uint32_t vslice = sb + OFF_V + wid * 32 * 128;
        const uint32_t pslice = sb + OFF_P + (wid >> 1) * 4096;
        const int pcb = (wid & 1) * 4;

        // ---- phase 1: QK MMA + exp2 + store unnormalized probs
#pragma unroll
        for (int kh = 0; kh < 2; kh++) {
            float sacc[2][2][4] = {};
            const int b_r = kh * 16 + (lane & 7) + ((lane >> 4) & 1) * 8;
#pragma unroll
            for (int ks = 0; ks < 4; ks++) {
                uint32_t bf[4];
                ldsm4(bf, kslice + swz16(b_r, ks * 2 + ((lane >> 3) & 1)));
#pragma unroll
                for (int mt = 0; mt < 2; mt++) {
                    mma_f16(sacc[mt][0], qf[mt][ks], bf);
                    mma_f16(sacc[mt][1], qf[mt][ks], bf + 2);
                }
            }
#pragma unroll
            for (int mt = 0; mt < 2; mt++)
#pragma unroll
                for (int n8 = 0; n8 < 2; n8++) {
                    float e0 = exp2f(sacc[mt][n8][0]);
                    float e1 = exp2f(sacc[mt][n8][1]);
                    float e2 = exp2f(sacc[mt][n8][2]);
                    float e3 = exp2f(sacc[mt][n8][3]);
                    __half2 p01 = __floats2half2_rn(e0, e1);
                    __half2 p23 = __floats2half2_rn(e2, e3);
                    const int row = mt * 16 + (lane >> 2);
                    const int chunk = pcb + kh * 2 + n8;
                    const int boff = ((lane & 3) * 2 & 7) * 2;
                    uint32_t a0 = pslice + (uint32_t)(row * 128) + (uint32_t)(((chunk ^ (row & 7)) << 4)) + boff;
                    uint32_t a1 = pslice + (uint32_t)((row + 8) * 128) + (uint32_t)(((chunk ^ ((row + 8) & 7)) << 4)) + boff;
                    asm volatile("st.shared.b32 [%0], %1;" :: "r"(a0), "r"(*(uint32_t*)&p01));
                    asm volatile("st.shared.b32 [%0], %1;" :: "r"(a1), "r"(*(uint32_t*)&p23));
                }
        }
        __syncthreads();

        // ---- phase 2: denominators -> inv (32q x 32k fp16)
        {
            float s0 = 0.f, s1 = 0.f;
#pragma unroll
            for (int h = 0; h < H_; h++) {
                int chunk = (h & 1) * 4 + (pk >> 3);
                uint32_t a = sb + OFF_P + (h >> 1) * 4096 + pq * 128
                           + (uint32_t)((chunk ^ (pq & 7)) << 4) + (pk & 7) * 2;
                uint32_t raw;
                asm volatile("ld.shared.b32 %0, [%1];" : "=r"(raw) : "r"(a));
                float2 f = __half22float2(*(__half2*)&raw);
                s0 += f.x; s1 += f.y;
            }
            __half2 iv = __floats2half2_rn(1.f / s0, 1.f / s1);
            asm volatile("st.shared.b32 [%0], %1;"
                :: "r"(sb + OFF_INV + pq * 80 + pk * 2), "r"(*(uint32_t*)&iv));
        }
        __syncthreads();

        // ---- phase 3: PV with on-the-fly normalization
#pragma unroll
        for (int kh = 0; kh < 2; kh++) {
            uint32_t pf[2][4];
#pragma unroll
            for (int mt = 0; mt < 2; mt++) {
                const int row = mt * 16 + (lane & 15);
                const int chunk = pcb + kh * 2 + (lane >> 4);
                ldsm4(pf[mt], pslice + (uint32_t)(row * 128) + (uint32_t)((chunk ^ (row & 7)) << 4));
                uint32_t ivf[4];
                ldsm4(ivf, sb + OFF_INV + row * 80 + kh * 32 + (lane >> 4) * 16);
#pragma unroll
                for (int j = 0; j < 4; j++) {
                    __half2 m = __hmul2(*(__half2*)&pf[mt][j], *(__half2*)&ivf[j]);
                    pf[mt][j] = *(uint32_t*)&m;
                }
            }
#pragma unroll
            for (int nt2 = 0; nt2 < 4; nt2++) {
                uint32_t bf[4];
                const int row = kh * 16 + (lane & 15);
                ldsm4t(bf, vslice + swz16(row, nt2 * 2 + (lane >> 4)));
                mma_f16(acc[0][nt2 * 2],     pf[0], bf);
                mma_f16(acc[0][nt2 * 2 + 1], pf[0], bf + 2);
                mma_f16(acc[1][nt2 * 2],     pf[1], bf);
                mma_f16(acc[1][nt2 * 2 + 1], pf[1], bf + 2);
            }
        }
        __syncthreads();

        if (kt + 1 < NIT) load_v(kt + 1);
        cp_commit();
        if (kt + 2 < NIT) load_k(kt + 2, stg);
        cp_commit();
    }

    // ---- epilogue
    const int col0 = wid * 64 + (lane & 3) * 2;
#pragma unroll
    for (int m = 0; m < 2; m++) {
        const int row = q0 + m * 16 + (lane >> 2);
#pragma unroll
        for (int n = 0; n < 8; n++) {
            const int col = col0 + n * 8;
            __half2 p0; p0.x = __float2half(acc[m][n][0]); p0.y = __float2half(acc[m][n][1]);
            __half2 p1; p1.x = __float2half(acc[m][n][2]); p1.y = __float2half(acc[m][n][3]);
            *(__half2*)(ctx16 + ((long long)(b * S_ + row)) * E_ + col)     = p0;
            *(__half2*)(ctx16 + ((long long)(b * S_ + row + 8)) * E_ + col) = p1;
        }
    }
}

// ---------------- launch ----------------
extern "C" void kernel_launch(void* const* d_in, const int* in_sizes, int n_in,
                              void* d_out, int out_size)
{
    const float* x  = (const float*)d_in[0];
    const float* Wq = (const float*)d_in[1];
    const float* bq = (const float*)d_in[2];
    const float* Wk = (const float*)d_in[3];
    const float* bk = (const float*)d_in[4];
    const float* Wv = (const float*)d_in[5];
    const float* bv = (const float*)d_in[6];
    const float* Wo = (const float*)d_in[7];
    const float* bo = (const float*)d_in[8];
    float* out = (float*)d_out;

    __half *x16, *wh16, *qkv16, *ctx16;
    cudaGetSymbolAddress((void**)&x16,  g_x16);
    cudaGetSymbolAddress((void**)&wh16, g_wh16);
    cudaGetSymbolAddress((void**)&qkv16, g_qkv16);
    cudaGetSymbolAddress((void**)&ctx16, g_ctx16);

    constexpr int SMEM_W1 = 3 * 2 * 128 * 80;   // 61440
    cudaFuncSetAttribute(gemm_w<128>, cudaFuncAttributeMaxDynamicSharedMemorySize, SMEM_W1);
    cudaFuncSetAttribute(attn_fused, cudaFuncAttributeMaxDynamicSharedMemorySize, ATT_SMEM);

    const int EE = E_ * E_;
    const long long QKV = (long long)NTOK * E_;
    __half* q16 = qkv16;
    __half* k16 = qkv16 + QKV;
    __half* v16 = qkv16 + 2 * QKV;
    const float SC = 0.125f * 1.4426950408889634f;

    // 1) convert all inputs in one launch (z=0: x, z=1..4: weights, hi only)
    prep_all_kernel<<<dim3(256, 5), 256>>>(x, Wq, Wk, Wv, Wo, x16, wh16);

    // 2) q,k,v projections (1-term fp16 weights; q scaled by SC)
    gemm_w<128><<<dim3(E_ / 128, NTOK / 128, 3), 512, SMEM_W1>>>(
        x16, wh16, bq, bk, bv,
        nullptr, qkv16, E_, E_, E_, E_, (long long)EE, QKV, SC);

    // 3) fused attention
    attn_fused<<<dim3(S_ / AQ, B_), 512, ATT_SMEM>>>(q16, k16, v16, ctx16);

    // 4) output projection (1-term weights) -> d_out (fp32)
    gemm_w<128><<<dim3(E_ / 128, NTOK / 128, 1), 512, SMEM_W1>>>(
        ctx16, wh16 + 3 * EE, bo, nullptr, nullptr,
        out, nullptr, E_, E_, E_, E_, 0, 0, 1.0f);
}

// round 15
// speedup vs baseline: 1.1874x; 1.0699x over previous
#include <cuda_runtime.h>
#include <cuda_fp16.h>
#include <cstdint>

#define B_   2
#define S_   2048
#define E_   1024
#define H_   16
#define D_   64
#define NTOK (B_*S_)

// ---------------- static scratch ----------------
__device__ __half g_x16 [NTOK*E_];
__device__ __half g_wh16[4*E_*E_];
__device__ __half g_qkv16[3LL*NTOK*E_];  // q | k | v
__device__ __half g_ctx16[NTOK*E_];

// ---------------- asm helpers ----------------
__device__ __forceinline__ uint32_t smem_u32(const void* p) {
    uint32_t a;
    asm("{ .reg .u64 t; cvta.to.shared.u64 t, %1; cvt.u32.u64 %0, t; }" : "=r"(a) : "l"(p));
    return a;
}
__device__ __forceinline__ void cp16(uint32_t dst, const void* src) {
    asm volatile("cp.async.cg.shared.global [%0], [%1], 16;" :: "r"(dst), "l"(src));
}
__device__ __forceinline__ void cp_commit() { asm volatile("cp.async.commit_group;"); }
__device__ __forceinline__ void cp_wait2()  { asm volatile("cp.async.wait_group 2;"); }
__device__ __forceinline__ void cp_wait1()  { asm volatile("cp.async.wait_group 1;"); }
__device__ __forceinline__ void cp_wait0()  { asm volatile("cp.async.wait_group 0;"); }
__device__ __forceinline__ void ldsm4(uint32_t* r, uint32_t addr) {
    asm volatile("ldmatrix.sync.aligned.m8n8.x4.shared.b16 {%0,%1,%2,%3}, [%4];"
        : "=r"(r[0]), "=r"(r[1]), "=r"(r[2]), "=r"(r[3]) : "r"(addr));
}
__device__ __forceinline__ void ldsm4t(uint32_t* r, uint32_t addr) {
    asm volatile("ldmatrix.sync.aligned.m8n8.x4.trans.shared.b16 {%0,%1,%2,%3}, [%4];"
        : "=r"(r[0]), "=r"(r[1]), "=r"(r[2]), "=r"(r[3]) : "r"(addr));
}
__device__ __forceinline__ void mma_f16(float* d, const uint32_t* a, const uint32_t* b) {
    asm volatile("mma.sync.aligned.m16n8k16.row.col.f32.f16.f16.f32 "
        "{%0,%1,%2,%3}, {%4,%5,%6,%7}, {%8,%9}, {%0,%1,%2,%3};"
        : "+f"(d[0]), "+f"(d[1]), "+f"(d[2]), "+f"(d[3])
        : "r"(a[0]), "r"(a[1]), "r"(a[2]), "r"(a[3]), "r"(b[0]), "r"(b[1]));
}
__device__ __forceinline__ uint32_t swz16(int row, int chunk) {
    return (uint32_t)(row * 128 + ((chunk ^ (row & 7)) << 4));
}

// ---------------- prep: x and all 4 weights -> fp16 in one launch ----------------
__global__ void prep_all_kernel(const float* __restrict__ x,
                                const float* __restrict__ w0, const float* __restrict__ w1,
                                const float* __restrict__ w2, const float* __restrict__ w3,
                                __half* __restrict__ x16, __half* __restrict__ wh16) {
    const int z = blockIdx.y;
    const float* src;
    __half* dst;
    int n;
    if (z == 0) { src = x;  dst = x16;              n = NTOK * E_; }
    else {
        src = (z == 1) ? w0 : (z == 2) ? w1 : (z == 3) ? w2 : w3;
        dst = wh16 + (z - 1) * (E_ * E_);
        n = E_ * E_;
    }
    for (int i = blockIdx.x * 256 + threadIdx.x; i < n; i += gridDim.x * 256)
        dst[i] = __float2half(src[i]);
}

// ---------------- 1-term fp16 GEMM, 3-stage pipeline, 2 blocks/SM ----------------
// C = (A @ B^T + bias) * (zh==0 ? zscale : 1); fp32 (Cf) or fp16 (C16) out.
// 512 threads, 16 warps 4m x 4n; warp tile 32x32; BM=BN=128, BK=32.
template <int BN>
__global__ __launch_bounds__(512, 2)
void gemm_w(const __half* __restrict__ A,
            const __half* __restrict__ Bhi,
            const float* __restrict__ bias0, const float* __restrict__ bias1,
            const float* __restrict__ bias2,
            float* __restrict__ Cf, __half* __restrict__ C16,
            int lda, int ldb, int ldc, int K,
            long long bH, long long cH, float zscale)
{
    extern __shared__ char smem[];
    constexpr int ASZ = 128 * 80;
    constexpr int OFF_B = ASZ;
    constexpr int STAGE = 2 * ASZ;       // 20480; 3 stages = 61440

    const int tid  = threadIdx.x;
    const int lane = tid & 31;
    const int wid  = tid >> 5;
    const int wm   = wid & 3;
    const int wn   = wid >> 2;
    const int zh   = blockIdx.z;
    const uint32_t sb = smem_u32(smem);
    const float* bias = (zh == 1) ? bias1 : ((zh == 2) ? bias2 : bias0);
    const float csc = (zh == 0) ? zscale : 1.0f;

    const __half* pA = A + (long long)blockIdx.y * 128 * lda;
    const __half* pB = Bhi + zh * bH + (long long)blockIdx.x * BN * ldb;

    const int r4 = tid >> 2, c4 = tid & 3;

    auto load_stage = [&](int kb, int stg) {
        uint32_t s0 = sb + stg * STAGE;
        cp16(s0 + r4 * 80 + c4 * 16, pA + (long long)r4 * lda + kb * 32 + c4 * 8);
        cp16(s0 + OFF_B + r4 * 80 + c4 * 16, pB + (long long)r4 * ldb + kb * 32 + c4 * 8);
    };

    const int KI = K >> 5;
    load_stage(0, 0); cp_commit();
    load_stage(1, 1); cp_commit();
    load_stage(2, 2); cp_commit();

    float acc[2][4][4] = {};

    const int a_r0 = wm * 32 + (lane & 15);
    const int a_c  = (lane >> 4) * 16;
    const int b_r  = wn * 32 + (lane & 7) + ((lane >> 4) & 1) * 8;
    const int b_c  = ((lane >> 3) & 1) * 16;

    int stg = 0;
    for (int kb = 0; kb < KI; kb++) {
        cp_wait2();
        __syncthreads();
        const uint32_t s0 = sb + stg * STAGE;
#pragma unroll
        for (int ks = 0; ks < 2; ks++) {
            const uint32_t koff = ks * 32;
            uint32_t ah[2][4], bh[2][4];
#pragma unroll
            for (int mt = 0; mt < 2; mt++)
                ldsm4(ah[mt], s0 + (a_r0 + mt * 16) * 80 + a_c + koff);
#pragma unroll
            for (int nt2 = 0; nt2 < 2; nt2++)
                ldsm4(bh[nt2], s0 + OFF_B + (b_r + nt2 * 16) * 80 + b_c + koff);
#pragma unroll
            for (int mt = 0; mt < 2; mt++)
#pragma unroll
                for (int nt2 = 0; nt2 < 2; nt2++) {
                    mma_f16(acc[mt][nt2 * 2],     ah[mt], bh[nt2]);
                    mma_f16(acc[mt][nt2 * 2 + 1], ah[mt], bh[nt2] + 2);
                }
        }
        __syncthreads();
        if (kb + 3 < KI) load_stage(kb + 3, stg);
        cp_commit();
        stg = (stg == 2) ? 0 : stg + 1;
    }

    const long long cb = zh * cH;
#pragma unroll
    for (int mt = 0; mt < 2; mt++) {
        const int mrow = blockIdx.y * 128 + wm * 32 + mt * 16 + (lane >> 2);
#pragma unroll
        for (int nt = 0; nt < 4; nt++) {
            const int col = blockIdx.x * BN + wn * 32 + nt * 8 + (lane & 3) * 2;
            float v0 = acc[mt][nt][0], v1 = acc[mt][nt][1];
            float v2 = acc[mt][nt][2], v3 = acc[mt][nt][3];
            if (bias) {
                float b0 = __ldg(&bias[col]), b1 = __ldg(&bias[col + 1]);
                v0 += b0; v1 += b1; v2 += b0; v3 += b1;
            }
            if (Cf) {
                *(float2*)(Cf + cb + (long long)mrow * ldc + col)       = make_float2(v0, v1);
                *(float2*)(Cf + cb + (long long)(mrow + 8) * ldc + col) = make_float2(v2, v3);
            } else {
                v0 *= csc; v1 *= csc; v2 *= csc; v3 *= csc;
                __half2 p0; p0.x = __float2half(v0); p0.y = __float2half(v1);
                __half2 p1; p1.x = __float2half(v2); p1.y = __float2half(v3);
                *(__half2*)(C16 + cb + (long long)mrow * ldc + col)       = p0;
                *(__half2*)(C16 + cb + (long long)(mrow + 8) * ldc + col) = p1;
            }
        }
    }
}

// ---------------- fully fused attention (round-12 validated version) ----------------
#define AQ 32
#define NIT (S_/32)                 // 64
#define OFF_K1  65536
#define OFF_V   131072
#define OFF_P   196608
#define OFF_INV 229376
#define ATT_SMEM 231936

__global__ __launch_bounds__(512, 1)
void attn_fused(const __half* __restrict__ q16, const __half* __restrict__ k16,
                const __half* __restrict__ v16, __half* __restrict__ ctx16)
{
    extern __shared__ char smem[];
    const int tid = threadIdx.x, lane = tid & 31, wid = tid >> 5;  // wid = head
    const int b = blockIdx.y, q0 = blockIdx.x * AQ;
    const uint32_t sb = smem_u32(smem);

    // ---- prologue: stage Q, hoist fragments (q already scaled by log2e/8)
#pragma unroll
    for (int p = 0; p < 8; p++) {
        int idx = tid + p * 512, r = idx >> 3, c = idx & 7;
        long long g = ((long long)(b * S_ + q0 + (r & 31))) * E_ + (r >> 5) * 64 + c * 8;
        cp16(sb + swz16(r, c), q16 + g);
    }
    cp_commit(); cp_wait0();
    __syncthreads();
    uint32_t qf[2][4][4];
#pragma unroll
    for (int mt = 0; mt < 2; mt++)
#pragma unroll
        for (int ks = 0; ks < 4; ks++) {
            int row = wid * 32 + mt * 16 + (lane & 15);
            ldsm4(qf[mt][ks], sb + swz16(row, ks * 2 + (lane >> 4)));
        }
    __syncthreads();

    auto load_k = [&](int kt, int stg) {
        const uint32_t d0 = sb + stg * OFF_K1;
#pragma unroll
        for (int p = 0; p < 8; p++) {
            int idx = tid + p * 512, r = idx >> 3, c = idx & 7;
            long long g = ((long long)(b * S_ + kt * 32 + (r & 31))) * E_ + (r >> 5) * 64 + c * 8;
            cp16(d0 + swz16(r, c), k16 + g);
        }
    };
    auto load_v = [&](int kt) {
        const uint32_t d0 = sb + OFF_V;
#pragma unroll
        for (int p = 0; p < 8; p++) {
            int idx = tid + p * 512, r = idx >> 3, c = idx & 7;
            long long g = ((long long)(b * S_ + kt * 32 + (r & 31))) * E_ + (r >> 5) * 64 + c * 8;
            cp16(d0 + swz16(r, c), v16 + g);
        }
    };

    load_k(0, 0); load_v(0); cp_commit();
    load_k(1, 1); cp_commit();

    float acc[2][8][4] = {};
    const int pq = tid >> 4, pk = (tid & 15) * 2;

    for (int kt = 0; kt < NIT; kt++) {
        cp_wait1();
        __syncthreads();
        const int stg = kt & 1;
        const uint32_t kslice = sb + stg * OFF_K1 + wid * 32 * 128;
        const uint32_t vslice = sb + OFF_V + wid * 32 * 128;
        const uint32_t pslice = sb + OFF_P + (wid >> 1) * 4096;
        const int pcb = (wid & 1) * 4;

        // ---- phase 1: QK MMA + exp2 + store unnormalized probs
#pragma unroll
        for (int kh = 0; kh < 2; kh++) {
            float sacc[2][2][4] = {};
            const int b_r = kh * 16 + (lane & 7) + ((lane >> 4) & 1) * 8;
#pragma unroll
            for (int ks = 0; ks < 4; ks++) {
                uint32_t bf[4];
                ldsm4(bf, kslice + swz16(b_r, ks * 2 + ((lane >> 3) & 1)));
#pragma unroll
                for (int mt = 0; mt < 2; mt++) {
                    mma_f16(sacc[mt][0], qf[mt][ks], bf);
                    mma_f16(sacc[mt][1], qf[mt][ks], bf + 2);
                }
            }
#pragma unroll
            for (int mt = 0; mt < 2; mt++)
#pragma unroll
                for (int n8 = 0; n8 < 2; n8++) {
                    float e0 = exp2f(sacc[mt][n8][0]);
                    float e1 = exp2f(sacc[mt][n8][1]);
                    float e2 = exp2f(sacc[mt][n8][2]);
                    float e3 = exp2f(sacc[mt][n8][3]);
                    __half2 p01 = __floats2half2_rn(e0, e1);
                    __half2 p23 = __floats2half2_rn(e2, e3);
                    const int row = mt * 16 + (lane >> 2);
                    const int chunk = pcb + kh * 2 + n8;
                    const int boff = ((lane & 3) * 2 & 7) * 2;
                    uint32_t a0 = pslice + (uint32_t)(row * 128) + (uint32_t)(((chunk ^ (row & 7)) << 4)) + boff;
                    uint32_t a1 = pslice + (uint32_t)((row + 8) * 128) + (uint32_t)(((chunk ^ ((row + 8) & 7)) << 4)) + boff;
                    asm volatile("st.shared.b32 [%0], %1;" :: "r"(a0), "r"(*(uint32_t*)&p01));
                    asm volatile("st.shared.b32 [%0], %1;" :: "r"(a1), "r"(*(uint32_t*)&p23));
                }
        }
        __syncthreads();

        // ---- phase 2: denominators -> inv (32q x 32k fp16)
        {
            float s0 = 0.f, s1 = 0.f;
#pragma unroll
            for (int h = 0; h < H_; h++) {
                int chunk = (h & 1) * 4 + (pk >> 3);
                uint32_t a = sb + OFF_P + (h >> 1) * 4096 + pq * 128
                           + (uint32_t)((chunk ^ (pq & 7)) << 4) + (pk & 7) * 2;
                uint32_t raw;
                asm volatile("ld.shared.b32 %0, [%1];" : "=r"(raw) : "r"(a));
                float2 f = __half22float2(*(__half2*)&raw);
                s0 += f.x; s1 += f.y;
            }
            __half2 iv = __floats2half2_rn(1.f / s0, 1.f / s1);
            asm volatile("st.shared.b32 [%0], %1;"
                :: "r"(sb + OFF_INV + pq * 80 + pk * 2), "r"(*(uint32_t*)&iv));
        }
        __syncthreads();

        // ---- phase 3: PV with on-the-fly normalization
#pragma unroll
        for (int kh = 0; kh < 2; kh++) {
            uint32_t pf[2][4];
#pragma unroll
            for (int mt = 0; mt < 2; mt++) {
                const int row = mt * 16 + (lane & 15);
                const int chunk = pcb + kh * 2 + (lane >> 4);
                ldsm4(pf[mt], pslice + (uint32_t)(row * 128) + (uint32_t)((chunk ^ (row & 7)) << 4));
                uint32_t ivf[4];
                ldsm4(ivf, sb + OFF_INV + row * 80 + kh * 32 + (lane >> 4) * 16);
#pragma unroll
                for (int j = 0; j < 4; j++) {
                    __half2 m = __hmul2(*(__half2*)&pf[mt][j], *(__half2*)&ivf[j]);
                    pf[mt][j] = *(uint32_t*)&m;
                }
            }
#pragma unroll
            for (int nt2 = 0; nt2 < 4; nt2++) {
                uint32_t bf[4];
                const int row = kh * 16 + (lane & 15);
                ldsm4t(bf, vslice + swz16(row, nt2 * 2 + (lane >> 4)));
                mma_f16(acc[0][nt2 * 2],     pf[0], bf);
                mma_f16(acc[0][nt2 * 2 + 1], pf[0], bf + 2);
                mma_f16(acc[1][nt2 * 2],     pf[1], bf);
                mma_f16(acc[1][nt2 * 2 + 1], pf[1], bf + 2);
            }
        }
        __syncthreads();

        if (kt + 1 < NIT) load_v(kt + 1);
        cp_commit();
        if (kt + 2 < NIT) load_k(kt + 2, stg);
        cp_commit();
    }

    // ---- epilogue
    const int col0 = wid * 64 + (lane & 3) * 2;
#pragma unroll
    for (int m = 0; m < 2; m++) {
        const int row = q0 + m * 16 + (lane >> 2);
#pragma unroll
        for (int n = 0; n < 8; n++) {
            const int col = col0 + n * 8;
            __half2 p0; p0.x = __float2half(acc[m][n][0]); p0.y = __float2half(acc[m][n][1]);
            __half2 p1; p1.x = __float2half(acc[m][n][2]); p1.y = __float2half(acc[m][n][3]);
            *(__half2*)(ctx16 + ((long long)(b * S_ + row)) * E_ + col)     = p0;
            *(__half2*)(ctx16 + ((long long)(b * S_ + row + 8)) * E_ + col) = p1;
        }
    }
}

// ---------------- launch ----------------
extern "C" void kernel_launch(void* const* d_in, const int* in_sizes, int n_in,
                              void* d_out, int out_size)
{
    const float* x  = (const float*)d_in[0];
    const float* Wq = (const float*)d_in[1];
    const float* bq = (const float*)d_in[2];
    const float* Wk = (const float*)d_in[3];
    const float* bk = (const float*)d_in[4];
    const float* Wv = (const float*)d_in[5];
    const float* bv = (const float*)d_in[6];
    const float* Wo = (const float*)d_in[7];
    const float* bo = (const float*)d_in[8];
    float* out = (float*)d_out;

    __half *x16, *wh16, *qkv16, *ctx16;
    cudaGetSymbolAddress((void**)&x16,  g_x16);
    cudaGetSymbolAddress((void**)&wh16, g_wh16);
    cudaGetSymbolAddress((void**)&qkv16, g_qkv16);
    cudaGetSymbolAddress((void**)&ctx16, g_ctx16);

    constexpr int SMEM_W1 = 3 * 2 * 128 * 80;   // 61440
    cudaFuncSetAttribute(gemm_w<128>, cudaFuncAttributeMaxDynamicSharedMemorySize, SMEM_W1);
    cudaFuncSetAttribute(attn_fused, cudaFuncAttributeMaxDynamicSharedMemorySize, ATT_SMEM);

    const int EE = E_ * E_;
    const long long QKV = (long long)NTOK * E_;
    __half* q16 = qkv16;
    __half* k16 = qkv16 + QKV;
    __half* v16 = qkv16 + 2 * QKV;
    const float SC = 0.125f * 1.4426950408889634f;

    // 1) convert all inputs in one launch (z=0: x, z=1..4: weights, hi only)
    prep_all_kernel<<<dim3(256, 5), 256>>>(x, Wq, Wk, Wv, Wo, x16, wh16);

    // 2) q,k,v projections (1-term fp16 weights; q scaled by SC)
    gemm_w<128><<<dim3(E_ / 128, NTOK / 128, 3), 512, SMEM_W1>>>(
        x16, wh16, bq, bk, bv,
        nullptr, qkv16, E_, E_, E_, E_, (long long)EE, QKV, SC);

    // 3) fused attention
    attn_fused<<<dim3(S_ / AQ, B_), 512, ATT_SMEM>>>(q16, k16, v16, ctx16);

    // 4) output projection (1-term weights) -> d_out (fp32)
    gemm_w<128><<<dim3(E_ / 128, NTOK / 128, 1), 512, SMEM_W1>>>(
        ctx16, wh16 + 3 * EE, bo, nullptr, nullptr,
        out, nullptr, E_, E_, E_, E_, 0, 0, 1.0f);
}

// round 16
// speedup vs baseline: 1.2581x; 1.0595x over previous
#include <cuda_runtime.h>
#include <cuda_fp16.h>
#include <cstdint>

#define B_   2
#define S_   2048
#define E_   1024
#define H_   16
#define D_   64
#define NTOK (B_*S_)

// ---------------- static scratch ----------------
__device__ __half g_x16 [NTOK*E_];
__device__ __half g_wh16[4*E_*E_];
__device__ __half g_qkv16[3LL*NTOK*E_];  // q | k | v
__device__ __half g_ctx16[NTOK*E_];

// ---------------- asm helpers ----------------
__device__ __forceinline__ uint32_t smem_u32(const void* p) {
    uint32_t a;
    asm("{ .reg .u64 t; cvta.to.shared.u64 t, %1; cvt.u32.u64 %0, t; }" : "=r"(a) : "l"(p));
    return a;
}
__device__ __forceinline__ void cp16(uint32_t dst, const void* src) {
    asm volatile("cp.async.cg.shared.global [%0], [%1], 16;" :: "r"(dst), "l"(src));
}
__device__ __forceinline__ void cp_commit() { asm volatile("cp.async.commit_group;"); }
__device__ __forceinline__ void cp_wait1()  { asm volatile("cp.async.wait_group 1;"); }
__device__ __forceinline__ void cp_wait0()  { asm volatile("cp.async.wait_group 0;"); }
__device__ __forceinline__ void ldsm4(uint32_t* r, uint32_t addr) {
    asm volatile("ldmatrix.sync.aligned.m8n8.x4.shared.b16 {%0,%1,%2,%3}, [%4];"
        : "=r"(r[0]), "=r"(r[1]), "=r"(r[2]), "=r"(r[3]) : "r"(addr));
}
__device__ __forceinline__ void ldsm4t(uint32_t* r, uint32_t addr) {
    asm volatile("ldmatrix.sync.aligned.m8n8.x4.trans.shared.b16 {%0,%1,%2,%3}, [%4];"
        : "=r"(r[0]), "=r"(r[1]), "=r"(r[2]), "=r"(r[3]) : "r"(addr));
}
__device__ __forceinline__ void mma_f16(float* d, const uint32_t* a, const uint32_t* b) {
    asm volatile("mma.sync.aligned.m16n8k16.row.col.f32.f16.f16.f32 "
        "{%0,%1,%2,%3}, {%4,%5,%6,%7}, {%8,%9}, {%0,%1,%2,%3};"
        : "+f"(d[0]), "+f"(d[1]), "+f"(d[2]), "+f"(d[3])
        : "r"(a[0]), "r"(a[1]), "r"(a[2]), "r"(a[3]), "r"(b[0]), "r"(b[1]));
}
__device__ __forceinline__ uint32_t swz16(int row, int chunk) {
    return (uint32_t)(row * 128 + ((chunk ^ (row & 7)) << 4));
}

// ---------------- prep: x and all 4 weights -> fp16 in one launch ----------------
__global__ void prep_all_kernel(const float* __restrict__ x,
                                const float* __restrict__ w0, const float* __restrict__ w1,
                                const float* __restrict__ w2, const float* __restrict__ w3,
                                __half* __restrict__ x16, __half* __restrict__ wh16) {
    const int z = blockIdx.y;
    const float* src;
    __half* dst;
    int n;
    if (z == 0) { src = x;  dst = x16;              n = NTOK * E_; }
    else {
        src = (z == 1) ? w0 : (z == 2) ? w1 : (z == 3) ? w2 : w3;
        dst = wh16 + (z - 1) * (E_ * E_);
        n = E_ * E_;
    }
    for (int i = blockIdx.x * 256 + threadIdx.x; i < n; i += gridDim.x * 256)
        dst[i] = __float2half(src[i]);
}

// ---------------- 1-term fp16 GEMM, BK=64, double-buffered, 2 blocks/SM ----------------
// C = (A @ B^T + bias) * (zh==0 ? zscale : 1); fp32 (Cf) or fp16 (C16) out.
// 512 threads, 16 warps 4m x 4n; warp tile 32x32; BM=BN=128, BK=64.
#define GROW 144                     // 128B data + 16B pad, conflict-free
#define GASZ (128 * GROW)            // 18432
#define GSTAGE (2 * GASZ)            // 36864; 2 stages = 73728

template <int BN>
__global__ __launch_bounds__(512, 2)
void gemm_w(const __half* __restrict__ A,
            const __half* __restrict__ Bhi,
            const float* __restrict__ bias0, const float* __restrict__ bias1,
            const float* __restrict__ bias2,
            float* __restrict__ Cf, __half* __restrict__ C16,
            int lda, int ldb, int ldc, int K,
            long long bH, long long cH, float zscale)
{
    extern __shared__ char smem[];
    const int tid  = threadIdx.x;
    const int lane = tid & 31;
    const int wid  = tid >> 5;
    const int wm   = wid & 3;
    const int wn   = wid >> 2;
    const int zh   = blockIdx.z;
    const uint32_t sb = smem_u32(smem);
    const float* bias = (zh == 1) ? bias1 : ((zh == 2) ? bias2 : bias0);
    const float csc = (zh == 0) ? zscale : 1.0f;

    const __half* pA = A + (long long)blockIdx.y * 128 * lda;
    const __half* pB = Bhi + zh * bH + (long long)blockIdx.x * BN * ldb;

    auto load_stage = [&](int kb, int stg) {
        uint32_t s0 = sb + stg * GSTAGE;
#pragma unroll
        for (int p = 0; p < 2; p++) {
            int idx = tid + p * 512;          // 0..1023
            int r = idx >> 3, c = idx & 7;
            cp16(s0 + r * GROW + c * 16,        pA + (long long)r * lda + kb * 64 + c * 8);
            cp16(s0 + GASZ + r * GROW + c * 16, pB + (long long)r * ldb + kb * 64 + c * 8);
        }
    };

    const int KI = K >> 6;                    // 16 for K=1024
    load_stage(0, 0); cp_commit();
    load_stage(1, 1); cp_commit();

    float acc[2][4][4] = {};

    const int a_r0 = wm * 32 + (lane & 15);
    const int a_c  = (lane >> 4) * 16;
    const int b_r  = wn * 32 + (lane & 7) + ((lane >> 4) & 1) * 8;
    const int b_c  = ((lane >> 3) & 1) * 16;

    for (int kb = 0; kb < KI; kb++) {
        cp_wait1();
        __syncthreads();
        const uint32_t s0 = sb + (kb & 1) * GSTAGE;
#pragma unroll
        for (int ks = 0; ks < 4; ks++) {
            const uint32_t koff = ks * 32;
            uint32_t ah[2][4], bh[2][4];
#pragma unroll
            for (int mt = 0; mt < 2; mt++)
                ldsm4(ah[mt], s0 + (a_r0 + mt * 16) * GROW + a_c + koff);
#pragma unroll
            for (int nt2 = 0; nt2 < 2; nt2++)
                ldsm4(bh[nt2], s0 + GASZ + (b_r + nt2 * 16) * GROW + b_c + koff);
#pragma unroll
            for (int mt = 0; mt < 2; mt++)
#pragma unroll
                for (int nt2 = 0; nt2 < 2; nt2++) {
                    mma_f16(acc[mt][nt2 * 2],     ah[mt], bh[nt2]);
                    mma_f16(acc[mt][nt2 * 2 + 1], ah[mt], bh[nt2] + 2);
                }
        }
        __syncthreads();
        if (kb + 2 < KI) load_stage(kb + 2, kb & 1);
        cp_commit();
    }

    const long long cb = zh * cH;
#pragma unroll
    for (int mt = 0; mt < 2; mt++) {
        const int mrow = blockIdx.y * 128 + wm * 32 + mt * 16 + (lane >> 2);
#pragma unroll
        for (int nt = 0; nt < 4; nt++) {
            const int col = blockIdx.x * BN + wn * 32 + nt * 8 + (lane & 3) * 2;
            float v0 = acc[mt][nt][0], v1 = acc[mt][nt][1];
            float v2 = acc[mt][nt][2], v3 = acc[mt][nt][3];
            if (bias) {
                float b0 = __ldg(&bias[col]), b1 = __ldg(&bias[col + 1]);
                v0 += b0; v1 += b1; v2 += b0; v3 += b1;
            }
            if (Cf) {
                *(float2*)(Cf + cb + (long long)mrow * ldc + col)       = make_float2(v0, v1);
                *(float2*)(Cf + cb + (long long)(mrow + 8) * ldc + col) = make_float2(v2, v3);
            } else {
                v0 *= csc; v1 *= csc; v2 *= csc; v3 *= csc;
                __half2 p0; p0.x = __float2half(v0); p0.y = __float2half(v1);
                __half2 p1; p1.x = __float2half(v2); p1.y = __float2half(v3);
                *(__half2*)(C16 + cb + (long long)mrow * ldc + col)       = p0;
                *(__half2*)(C16 + cb + (long long)(mrow + 8) * ldc + col) = p1;
            }
        }
    }
}

// ---------------- fully fused attention (round-12 validated version) ----------------
#define AQ 32
#define NIT (S_/32)                 // 64
#define OFF_K1  65536
#define OFF_V   131072
#define OFF_P   196608
#define OFF_INV 229376
#define ATT_SMEM 231936

__global__ __launch_bounds__(512, 1)
void attn_fused(const __half* __restrict__ q16, const __half* __restrict__ k16,
                const __half* __restrict__ v16, __half* __restrict__ ctx16)
{
    extern __shared__ char smem[];
    const int tid = threadIdx.x, lane = tid & 31, wid = tid >> 5;  // wid = head
    const int b = blockIdx.y, q0 = blockIdx.x * AQ;
    const uint32_t sb = smem_u32(smem);

    // ---- prologue: stage Q, hoist fragments (q already scaled by log2e/8)
#pragma unroll
    for (int p = 0; p < 8; p++) {
        int idx = tid + p * 512, r = idx >> 3, c = idx & 7;
        long long g = ((long long)(b * S_ + q0 + (r & 31))) * E_ + (r >> 5) * 64 + c * 8;
        cp16(sb + swz16(r, c), q16 + g);
    }
    cp_commit(); cp_wait0();
    __syncthreads();
    uint32_t qf[2][4][4];
#pragma unroll
    for (int mt = 0; mt < 2; mt++)
#pragma unroll
        for (int ks = 0; ks < 4; ks++) {
            int row = wid * 32 + mt * 16 + (lane & 15);
            ldsm4(qf[mt][ks], sb + swz16(row, ks * 2 + (lane >> 4)));
        }
    __syncthreads();

    auto load_k = [&](int kt, int stg) {
        const uint32_t d0 = sb + stg * OFF_K1;
#pragma unroll
        for (int p = 0; p < 8; p++) {
            int idx = tid + p * 512, r = idx >> 3, c = idx & 7;
            long long g = ((long long)(b * S_ + kt * 32 + (r & 31))) * E_ + (r >> 5) * 64 + c * 8;
            cp16(d0 + swz16(r, c), k16 + g);
        }
    };
    auto load_v = [&](int kt) {
        const uint32_t d0 = sb + OFF_V;
#pragma unroll
        for (int p = 0; p < 8; p++) {
            int idx = tid + p * 512, r = idx >> 3, c = idx & 7;
            long long g = ((long long)(b * S_ + kt * 32 + (r & 31))) * E_ + (r >> 5) * 64 + c * 8;
            cp16(d0 + swz16(r, c), v16 + g);
        }
    };

    load_k(0, 0); load_v(0); cp_commit();
    load_k(1, 1); cp_commit();

    float acc[2][8][4] = {};
    const int pq = tid >> 4, pk = (tid & 15) * 2;

    for (int kt = 0; kt < NIT; kt++) {
        cp_wait1();
        __syncthreads();
        const int stg = kt & 1;
        const uint32_t kslice = sb + stg * OFF_K1 + wid * 32 * 128;
        const uint32_t vslice = sb + OFF_V + wid * 32 * 128;
        const uint32_t pslice = sb + OFF_P + (wid >> 1) * 4096;
        const int pcb = (wid & 1) * 4;

        // ---- phase 1: QK MMA + exp2 + store unnormalized probs
#pragma unroll
        for (int kh = 0; kh < 2; kh++) {
            float sacc[2][2][4] = {};
            const int b_r = kh * 16 + (lane & 7) + ((lane >> 4) & 1) * 8;
#pragma unroll
            for (int ks = 0; ks < 4; ks++) {
                uint32_t bf[4];
                ldsm4(bf, kslice + swz16(b_r, ks * 2 + ((lane >> 3) & 1)));
#pragma unroll
                for (int mt = 0; mt < 2; mt++) {
                    mma_f16(sacc[mt][0], qf[mt][ks], bf);
                    mma_f16(sacc[mt][1], qf[mt][ks], bf + 2);
                }
            }
#pragma unroll
            for (int mt = 0; mt < 2; mt++)
#pragma unroll
                for (int n8 = 0; n8 < 2; n8++) {
                    float e0 = exp2f(sacc[mt][n8][0]);
                    float e1 = exp2f(sacc[mt][n8][1]);
                    float e2 = exp2f(sacc[mt][n8][2]);
                    float e3 = exp2f(sacc[mt][n8][3]);
                    __half2 p01 = __floats2half2_rn(e0, e1);
                    __half2 p23 = __floats2half2_rn(e2, e3);
                    const int row = mt * 16 + (lane >> 2);
                    const int chunk = pcb + kh * 2 + n8;
                    const int boff = ((lane & 3) * 2 & 7) * 2;
                    uint32_t a0 = pslice + (uint32_t)(row * 128) + (uint32_t)(((chunk ^ (row & 7)) << 4)) + boff;
                    uint32_t a1 = pslice + (uint32_t)((row + 8) * 128) + (uint32_t)(((chunk ^ ((row + 8) & 7)) << 4)) + boff;
                    asm volatile("st.shared.b32 [%0], %1;" :: "r"(a0), "r"(*(uint32_t*)&p01));
                    asm volatile("st.shared.b32 [%0], %1;" :: "r"(a1), "r"(*(uint32_t*)&p23));
                }
        }
        __syncthreads();

        // ---- phase 2: denominators -> inv (32q x 32k fp16)
        {
            float s0 = 0.f, s1 = 0.f;
#pragma unroll
            for (int h = 0; h < H_; h++) {
                int chunk = (h & 1) * 4 + (pk >> 3);
                uint32_t a = sb + OFF_P + (h >> 1) * 4096 + pq * 128
                           + (uint32_t)((chunk ^ (pq & 7)) << 4) + (pk & 7) * 2;
                uint32_t raw;
                asm volatile("ld.shared.b32 %0, [%1];" : "=r"(raw) : "r"(a));
                float2 f = __half22float2(*(__half2*)&raw);
                s0 += f.x; s1 += f.y;
            }
            __half2 iv = __floats2half2_rn(1.f / s0, 1.f / s1);
            asm volatile("st.shared.b32 [%0], %1;"
                :: "r"(sb + OFF_INV + pq * 80 + pk * 2), "r"(*(uint32_t*)&iv));
        }
        __syncthreads();

        // ---- phase 3: PV with on-the-fly normalization
#pragma unroll
        for (int kh = 0; kh < 2; kh++) {
            uint32_t pf[2][4];
#pragma unroll
            for (int mt = 0; mt < 2; mt++) {
                const int row = mt * 16 + (lane & 15);
                const int chunk = pcb + kh * 2 + (lane >> 4);
                ldsm4(pf[mt], pslice + (uint32_t)(row * 128) + (uint32_t)((chunk ^ (row & 7)) << 4));
                uint32_t ivf[4];
                ldsm4(ivf, sb + OFF_INV + row * 80 + kh * 32 + (lane >> 4) * 16);
#pragma unroll
                for (int j = 0; j < 4; j++) {
                    __half2 m = __hmul2(*(__half2*)&pf[mt][j], *(__half2*)&ivf[j]);
                    pf[mt][j] = *(uint32_t*)&m;
                }
            }
#pragma unroll
            for (int nt2 = 0; nt2 < 4; nt2++) {
                uint32_t bf[4];
                const int row = kh * 16 + (lane & 15);
                ldsm4t(bf, vslice + swz16(row, nt2 * 2 + (lane >> 4)));
                mma_f16(acc[0][nt2 * 2],     pf[0], bf);
                mma_f16(acc[0][nt2 * 2 + 1], pf[0], bf + 2);
                mma_f16(acc[1][nt2 * 2],     pf[1], bf);
                mma_f16(acc[1][nt2 * 2 + 1], pf[1], bf + 2);
            }
        }
        __syncthreads();

        if (kt + 1 < NIT) load_v(kt + 1);
        cp_commit();
        if (kt + 2 < NIT) load_k(kt + 2, stg);
        cp_commit();
    }

    // ---- epilogue
    const int col0 = wid * 64 + (lane & 3) * 2;
#pragma unroll
    for (int m = 0; m < 2; m++) {
        const int row = q0 + m * 16 + (lane >> 2);
#pragma unroll
        for (int n = 0; n < 8; n++) {
            const int col = col0 + n * 8;
            __half2 p0; p0.x = __float2half(acc[m][n][0]); p0.y = __float2half(acc[m][n][1]);
            __half2 p1; p1.x = __float2half(acc[m][n][2]); p1.y = __float2half(acc[m][n][3]);
            *(__half2*)(ctx16 + ((long long)(b * S_ + row)) * E_ + col)     = p0;
            *(__half2*)(ctx16 + ((long long)(b * S_ + row + 8)) * E_ + col) = p1;
        }
    }
}

// ---------------- launch ----------------
extern "C" void kernel_launch(void* const* d_in, const int* in_sizes, int n_in,
                              void* d_out, int out_size)
{
    const float* x  = (const float*)d_in[0];
    const float* Wq = (const float*)d_in[1];
    const float* bq = (const float*)d_in[2];
    const float* Wk = (const float*)d_in[3];
    const float* bk = (const float*)d_in[4];
    const float* Wv = (const float*)d_in[5];
    const float* bv = (const float*)d_in[6];
    const float* Wo = (const float*)d_in[7];
    const float* bo = (const float*)d_in[8];
    float* out = (float*)d_out;

    __half *x16, *wh16, *qkv16, *ctx16;
    cudaGetSymbolAddress((void**)&x16,  g_x16);
    cudaGetSymbolAddress((void**)&wh16, g_wh16);
    cudaGetSymbolAddress((void**)&qkv16, g_qkv16);
    cudaGetSymbolAddress((void**)&ctx16, g_ctx16);

    constexpr int SMEM_G = 2 * GSTAGE;   // 73728
    cudaFuncSetAttribute(gemm_w<128>, cudaFuncAttributeMaxDynamicSharedMemorySize, SMEM_G);
    cudaFuncSetAttribute(attn_fused, cudaFuncAttributeMaxDynamicSharedMemorySize, ATT_SMEM);

    const int EE = E_ * E_;
    const long long QKV = (long long)NTOK * E_;
    __half* q16 = qkv16;
    __half* k16 = qkv16 + QKV;
    __half* v16 = qkv16 + 2 * QKV;
    const float SC = 0.125f * 1.4426950408889634f;

    // 1) convert all inputs in one launch (z=0: x, z=1..4: weights)
    prep_all_kernel<<<dim3(256, 5), 256>>>(x, Wq, Wk, Wv, Wo, x16, wh16);

    // 2) q,k,v projections (1-term fp16 weights; q scaled by SC)
    gemm_w<128><<<dim3(E_ / 128, NTOK / 128, 3), 512, SMEM_G>>>(
        x16, wh16, bq, bk, bv,
        nullptr, qkv16, E_, E_, E_, E_, (long long)EE, QKV, SC);

    // 3) fused attention
    attn_fused<<<dim3(S_ / AQ, B_), 512, ATT_SMEM>>>(q16, k16, v16, ctx16);

    // 4) output projection (1-term weights) -> d_out (fp32)
    gemm_w<128><<<dim3(E_ / 128, NTOK / 128, 1), 512, SMEM_G>>>(
        ctx16, wh16 + 3 * EE, bo, nullptr, nullptr,
        out, nullptr, E_, E_, E_, E_, 0, 0, 1.0f);
}

// round 17
// speedup vs baseline: 1.3166x; 1.0466x over previous
#include <cuda_runtime.h>
#include <cuda_fp16.h>
#include <cstdint>

#define B_   2
#define S_   2048
#define E_   1024
#define H_   16
#define D_   64
#define NTOK (B_*S_)

// ---------------- static scratch ----------------
__device__ __half g_x16 [NTOK*E_];
__device__ __half g_wh16[4*E_*E_];
__device__ __half g_qkv16[3LL*NTOK*E_];  // q | k | v
__device__ __half g_ctx16[NTOK*E_];

// ---------------- asm helpers ----------------
__device__ __forceinline__ uint32_t smem_u32(const void* p) {
    uint32_t a;
    asm("{ .reg .u64 t; cvta.to.shared.u64 t, %1; cvt.u32.u64 %0, t; }" : "=r"(a) : "l"(p));
    return a;
}
__device__ __forceinline__ void cp16(uint32_t dst, const void* src) {
    asm volatile("cp.async.cg.shared.global [%0], [%1], 16;" :: "r"(dst), "l"(src));
}
__device__ __forceinline__ void cp_commit() { asm volatile("cp.async.commit_group;"); }
__device__ __forceinline__ void cp_wait1()  { asm volatile("cp.async.wait_group 1;"); }
__device__ __forceinline__ void cp_wait0()  { asm volatile("cp.async.wait_group 0;"); }
__device__ __forceinline__ void ldsm4(uint32_t* r, uint32_t addr) {
    asm volatile("ldmatrix.sync.aligned.m8n8.x4.shared.b16 {%0,%1,%2,%3}, [%4];"
        : "=r"(r[0]), "=r"(r[1]), "=r"(r[2]), "=r"(r[3]) : "r"(addr));
}
__device__ __forceinline__ void ldsm4t(uint32_t* r, uint32_t addr) {
    asm volatile("ldmatrix.sync.aligned.m8n8.x4.trans.shared.b16 {%0,%1,%2,%3}, [%4];"
        : "=r"(r[0]), "=r"(r[1]), "=r"(r[2]), "=r"(r[3]) : "r"(addr));
}
__device__ __forceinline__ void mma_f16(float* d, const uint32_t* a, const uint32_t* b) {
    asm volatile("mma.sync.aligned.m16n8k16.row.col.f32.f16.f16.f32 "
        "{%0,%1,%2,%3}, {%4,%5,%6,%7}, {%8,%9}, {%0,%1,%2,%3};"
        : "+f"(d[0]), "+f"(d[1]), "+f"(d[2]), "+f"(d[3])
        : "r"(a[0]), "r"(a[1]), "r"(a[2]), "r"(a[3]), "r"(b[0]), "r"(b[1]));
}
__device__ __forceinline__ uint32_t swz16(int row, int chunk) {
    return (uint32_t)(row * 128 + ((chunk ^ (row & 7)) << 4));
}
__device__ __forceinline__ uint32_t ex2_f16x2(uint32_t a) {
    uint32_t r;
    asm volatile("ex2.approx.f16x2 %0, %1;" : "=r"(r) : "r"(a));
    return r;
}

// ---------------- prep: x and all 4 weights -> fp16 in one launch ----------------
__global__ void prep_all_kernel(const float* __restrict__ x,
                                const float* __restrict__ w0, const float* __restrict__ w1,
                                const float* __restrict__ w2, const float* __restrict__ w3,
                                __half* __restrict__ x16, __half* __restrict__ wh16) {
    const int z = blockIdx.y;
    const float* src;
    __half* dst;
    int n;
    if (z == 0) { src = x;  dst = x16;              n = NTOK * E_; }
    else {
        src = (z == 1) ? w0 : (z == 2) ? w1 : (z == 3) ? w2 : w3;
        dst = wh16 + (z - 1) * (E_ * E_);
        n = E_ * E_;
    }
    for (int i = blockIdx.x * 256 + threadIdx.x; i < n; i += gridDim.x * 256)
        dst[i] = __float2half(src[i]);
}

// ---------------- 1-term fp16 GEMM, BK=64, 256 thr, warp tile 32x64 ----------------
// C = (A @ B^T + bias) * (zh==0 ? zscale : 1); fp32 (Cf) or fp16 (C16) out.
// 8 warps 4m x 2n; BM=BN=128, BK=64; 2 blocks/SM.
#define GROW 144
#define GASZ (128 * GROW)            // 18432
#define GSTAGE (2 * GASZ)            // 36864; 2 stages = 73728

template <int BN>
__global__ __launch_bounds__(256, 2)
void gemm_w(const __half* __restrict__ A,
            const __half* __restrict__ Bhi,
            const float* __restrict__ bias0, const float* __restrict__ bias1,
            const float* __restrict__ bias2,
            float* __restrict__ Cf, __half* __restrict__ C16,
            int lda, int ldb, int ldc, int K,
            long long bH, long long cH, float zscale)
{
    extern __shared__ char smem[];
    const int tid  = threadIdx.x;
    const int lane = tid & 31;
    const int wid  = tid >> 5;
    const int wm   = wid & 3;                 // 4 m-warps
    const int wn   = wid >> 2;                // 2 n-warps
    const int zh   = blockIdx.z;
    const uint32_t sb = smem_u32(smem);
    const float* bias = (zh == 1) ? bias1 : ((zh == 2) ? bias2 : bias0);
    const float csc = (zh == 0) ? zscale : 1.0f;

    const __half* pA = A + (long long)blockIdx.y * 128 * lda;
    const __half* pB = Bhi + zh * bH + (long long)blockIdx.x * BN * ldb;

    auto load_stage = [&](int kb, int stg) {
        uint32_t s0 = sb + stg * GSTAGE;
#pragma unroll
        for (int p = 0; p < 4; p++) {
            int idx = tid + p * 256;          // 0..1023
            int r = idx >> 3, c = idx & 7;
            cp16(s0 + r * GROW + c * 16,        pA + (long long)r * lda + kb * 64 + c * 8);
            cp16(s0 + GASZ + r * GROW + c * 16, pB + (long long)r * ldb + kb * 64 + c * 8);
        }
    };

    const int KI = K >> 6;                    // 16 for K=1024
    load_stage(0, 0); cp_commit();
    load_stage(1, 1); cp_commit();

    float acc[2][8][4] = {};                  // [m-tile][n8-tile][4]

    const int a_r0 = wm * 32 + (lane & 15);
    const int a_c  = (lane >> 4) * 16;
    const int b_r  = wn * 64 + (lane & 7) + ((lane >> 4) & 1) * 8;
    const int b_c  = ((lane >> 3) & 1) * 16;

    for (int kb = 0; kb < KI; kb++) {
        cp_wait1();
        __syncthreads();
        const uint32_t s0 = sb + (kb & 1) * GSTAGE;
#pragma unroll
        for (int ks = 0; ks < 4; ks++) {
            const uint32_t koff = ks * 32;
            uint32_t ah[2][4], bh[4][4];
#pragma unroll
            for (int mt = 0; mt < 2; mt++)
                ldsm4(ah[mt], s0 + (a_r0 + mt * 16) * GROW + a_c + koff);
#pragma unroll
            for (int nt2 = 0; nt2 < 4; nt2++)
                ldsm4(bh[nt2], s0 + GASZ + (b_r + nt2 * 16) * GROW + b_c + koff);
#pragma unroll
            for (int mt = 0; mt < 2; mt++)
#pragma unroll
                for (int nt2 = 0; nt2 < 4; nt2++) {
                    mma_f16(acc[mt][nt2 * 2],     ah[mt], bh[nt2]);
                    mma_f16(acc[mt][nt2 * 2 + 1], ah[mt], bh[nt2] + 2);
                }
        }
        __syncthreads();
        if (kb + 2 < KI) load_stage(kb + 2, kb & 1);
        cp_commit();
    }

    const long long cb = zh * cH;
#pragma unroll
    for (int mt = 0; mt < 2; mt++) {
        const int mrow = blockIdx.y * 128 + wm * 32 + mt * 16 + (lane >> 2);
#pragma unroll
        for (int nt = 0; nt < 8; nt++) {
            const int col = blockIdx.x * BN + wn * 64 + nt * 8 + (lane & 3) * 2;
            float v0 = acc[mt][nt][0], v1 = acc[mt][nt][1];
            float v2 = acc[mt][nt][2], v3 = acc[mt][nt][3];
            if (bias) {
                float b0 = __ldg(&bias[col]), b1 = __ldg(&bias[col + 1]);
                v0 += b0; v1 += b1; v2 += b0; v3 += b1;
            }
            if (Cf) {
                *(float2*)(Cf + cb + (long long)mrow * ldc + col)       = make_float2(v0, v1);
                *(float2*)(Cf + cb + (long long)(mrow + 8) * ldc + col) = make_float2(v2, v3);
            } else {
                v0 *= csc; v1 *= csc; v2 *= csc; v3 *= csc;
                __half2 p0; p0.x = __float2half(v0); p0.y = __float2half(v1);
                __half2 p1; p1.x = __float2half(v2); p1.y = __float2half(v3);
                *(__half2*)(C16 + cb + (long long)mrow * ldc + col)       = p0;
                *(__half2*)(C16 + cb + (long long)(mrow + 8) * ldc + col) = p1;
            }
        }
    }
}

// ---------------- fully fused attention (ex2.approx.f16x2 exps) ----------------
#define AQ 32
#define NIT (S_/32)                 // 64
#define OFF_K1  65536
#define OFF_V   131072
#define OFF_P   196608
#define OFF_INV 229376
#define ATT_SMEM 231936

__global__ __launch_bounds__(512, 1)
void attn_fused(const __half* __restrict__ q16, const __half* __restrict__ k16,
                const __half* __restrict__ v16, __half* __restrict__ ctx16)
{
    extern __shared__ char smem[];
    const int tid = threadIdx.x, lane = tid & 31, wid = tid >> 5;  // wid = head
    const int b = blockIdx.y, q0 = blockIdx.x * AQ;
    const uint32_t sb = smem_u32(smem);

    // ---- prologue: stage Q, hoist fragments (q already scaled by log2e/8)
#pragma unroll
    for (int p = 0; p < 8; p++) {
        int idx = tid + p * 512, r = idx >> 3, c = idx & 7;
        long long g = ((long long)(b * S_ + q0 + (r & 31))) * E_ + (r >> 5) * 64 + c * 8;
        cp16(sb + swz16(r, c), q16 + g);
    }
    cp_commit(); cp_wait0();
    __syncthreads();
    uint32_t qf[2][4][4];
#pragma unroll
    for (int mt = 0; mt < 2; mt++)
#pragma unroll
        for (int ks = 0; ks < 4; ks++) {
            int row = wid * 32 + mt * 16 + (lane & 15);
            ldsm4(qf[mt][ks], sb + swz16(row, ks * 2 + (lane >> 4)));
        }
    __syncthreads();

    auto load_k = [&](int kt, int stg) {
        const uint32_t d0 = sb + stg * OFF_K1;
#pragma unroll
        for (int p = 0; p < 8; p++) {
            int idx = tid + p * 512, r = idx >> 3, c = idx & 7;
            long long g = ((long long)(b * S_ + kt * 32 + (r & 31))) * E_ + (r >> 5) * 64 + c * 8;
            cp16(d0 + swz16(r, c), k16 + g);
        }
    };
    auto load_v = [&](int kt) {
        const uint32_t d0 = sb + OFF_V;
#pragma unroll
        for (int p = 0; p < 8; p++) {
            int idx = tid + p * 512, r = idx >> 3, c = idx & 7;
            long long g = ((long long)(b * S_ + kt * 32 + (r & 31))) * E_ + (r >> 5) * 64 + c * 8;
            cp16(d0 + swz16(r, c), v16 + g);
        }
    };

    load_k(0, 0); load_v(0); cp_commit();
    load_k(1, 1); cp_commit();

    float acc[2][8][4] = {};
    const int pq = tid >> 4, pk = (tid & 15) * 2;

    for (int kt = 0; kt < NIT; kt++) {
        cp_wait1();
        __syncthreads();
        const int stg = kt & 1;
        const uint32_t kslice = sb + stg * OFF_K1 + wid * 32 * 128;
        const uint32_t vslice = sb + OFF_V + wid * 32 * 128;
        const uint32_t pslice = sb + OFF_P + (wid >> 1) * 4096;
        const int pcb = (wid & 1) * 4;

        // ---- phase 1: QK MMA + ex2.f16x2 + store unnormalized probs
#pragma unroll
        for (int kh = 0; kh < 2; kh++) {
            float sacc[2][2][4] = {};
            const int b_r = kh * 16 + (lane & 7) + ((lane >> 4) & 1) * 8;
#pragma unroll
            for (int ks = 0; ks < 4; ks++) {
                uint32_t bf[4];
                ldsm4(bf, kslice + swz16(b_r, ks * 2 + ((lane >> 3) & 1)));
#pragma unroll
                for (int mt = 0; mt < 2; mt++) {
                    mma_f16(sacc[mt][0], qf[mt][ks], bf);
                    mma_f16(sacc[mt][1], qf[mt][ks], bf + 2);
                }
            }
#pragma unroll
            for (int mt = 0; mt < 2; mt++)
#pragma unroll
                for (int n8 = 0; n8 < 2; n8++) {
                    __half2 a01 = __floats2half2_rn(sacc[mt][n8][0], sacc[mt][n8][1]);
                    __half2 a23 = __floats2half2_rn(sacc[mt][n8][2], sacc[mt][n8][3]);
                    uint32_t p01 = ex2_f16x2(*(uint32_t*)&a01);
                    uint32_t p23 = ex2_f16x2(*(uint32_t*)&a23);
                    const int row = mt * 16 + (lane >> 2);
                    const int chunk = pcb + kh * 2 + n8;
                    const int boff = ((lane & 3) * 2 & 7) * 2;
                    uint32_t a0 = pslice + (uint32_t)(row * 128) + (uint32_t)(((chunk ^ (row & 7)) << 4)) + boff;
                    uint32_t a1 = pslice + (uint32_t)((row + 8) * 128) + (uint32_t)(((chunk ^ ((row + 8) & 7)) << 4)) + boff;
                    asm volatile("st.shared.b32 [%0], %1;" :: "r"(a0), "r"(p01));
                    asm volatile("st.shared.b32 [%0], %1;" :: "r"(a1), "r"(p23));
                }
        }
        __syncthreads();

        // ---- phase 2: denominators -> inv (32q x 32k fp16)
        {
            float s0 = 0.f, s1 = 0.f;
#pragma unroll
            for (int h = 0; h < H_; h++) {
                int chunk = (h & 1) * 4 + (pk >> 3);
                uint32_t a = sb + OFF_P + (h >> 1) * 4096 + pq * 128
                           + (uint32_t)((chunk ^ (pq & 7)) << 4) + (pk & 7) * 2;
                uint32_t raw;
                asm volatile("ld.shared.b32 %0, [%1];" : "=r"(raw) : "r"(a));
                float2 f = __half22float2(*(__half2*)&raw);
                s0 += f.x; s1 += f.y;
            }
            __half2 iv = __floats2half2_rn(1.f / s0, 1.f / s1);
            asm volatile("st.shared.b32 [%0], %1;"
                :: "r"(sb + OFF_INV + pq * 80 + pk * 2), "r"(*(uint32_t*)&iv));
        }
        __syncthreads();

        // ---- phase 3: PV with on-the-fly normalization
#pragma unroll
        for (int kh = 0; kh < 2; kh++) {
            uint32_t pf[2][4];
#pragma unroll
            for (int mt = 0; mt < 2; mt++) {
                const int row = mt * 16 + (lane & 15);
                const int chunk = pcb + kh * 2 + (lane >> 4);
                ldsm4(pf[mt], pslice + (uint32_t)(row * 128) + (uint32_t)((chunk ^ (row & 7)) << 4));
                uint32_t ivf[4];
                ldsm4(ivf, sb + OFF_INV + row * 80 + kh * 32 + (lane >> 4) * 16);
#pragma unroll
                for (int j = 0; j < 4; j++) {
                    __half2 m = __hmul2(*(__half2*)&pf[mt][j], *(__half2*)&ivf[j]);
                    pf[mt][j] = *(uint32_t*)&m;
                }
            }
#pragma unroll
            for (int nt2 = 0; nt2 < 4; nt2++) {
                uint32_t bf[4];
                const int row = kh * 16 + (lane & 15);
                ldsm4t(bf, vslice + swz16(row, nt2 * 2 + (lane >> 4)));
                mma_f16(acc[0][nt2 * 2],     pf[0], bf);
                mma_f16(acc[0][nt2 * 2 + 1], pf[0], bf + 2);
                mma_f16(acc[1][nt2 * 2],     pf[1], bf);
                mma_f16(acc[1][nt2 * 2 + 1], pf[1], bf + 2);
            }
        }
        __syncthreads();

        if (kt + 1 < NIT) load_v(kt + 1);
        cp_commit();
        if (kt + 2 < NIT) load_k(kt + 2, stg);
        cp_commit();
    }

    // ---- epilogue
    const int col0 = wid * 64 + (lane & 3) * 2;
#pragma unroll
    for (int m = 0; m < 2; m++) {
        const int row = q0 + m * 16 + (lane >> 2);
#pragma unroll
        for (int n = 0; n < 8; n++) {
            const int col = col0 + n * 8;
            __half2 p0; p0.x = __float2half(acc[m][n][0]); p0.y = __float2half(acc[m][n][1]);
            __half2 p1; p1.x = __float2half(acc[m][n][2]); p1.y = __float2half(acc[m][n][3]);
            *(__half2*)(ctx16 + ((long long)(b * S_ + row)) * E_ + col)     = p0;
            *(__half2*)(ctx16 + ((long long)(b * S_ + row + 8)) * E_ + col) = p1;
        }
    }
}

// ---------------- launch ----------------
extern "C" void kernel_launch(void* const* d_in, const int* in_sizes, int n_in,
                              void* d_out, int out_size)
{
    const float* x  = (const float*)d_in[0];
    const float* Wq = (const float*)d_in[1];
    const float* bq = (const float*)d_in[2];
    const float* Wk = (const float*)d_in[3];
    const float* bk = (const float*)d_in[4];
    const float* Wv = (const float*)d_in[5];
    const float* bv = (const float*)d_in[6];
    const float* Wo = (const float*)d_in[7];
    const float* bo = (const float*)d_in[8];
    float* out = (float*)d_out;

    __half *x16, *wh16, *qkv16, *ctx16;
    cudaGetSymbolAddress((void**)&x16,  g_x16);
    cudaGetSymbolAddress((void**)&wh16, g_wh16);
    cudaGetSymbolAddress((void**)&qkv16, g_qkv16);
    cudaGetSymbolAddress((void**)&ctx16, g_ctx16);

    constexpr int SMEM_G = 2 * GSTAGE;   // 73728
    cudaFuncSetAttribute(gemm_w<128>, cudaFuncAttributeMaxDynamicSharedMemorySize, SMEM_G);
    cudaFuncSetAttribute(attn_fused, cudaFuncAttributeMaxDynamicSharedMemorySize, ATT_SMEM);

    const int EE = E_ * E_;
    const long long QKV = (long long)NTOK * E_;
    __half* q16 = qkv16;
    __half* k16 = qkv16 + QKV;
    __half* v16 = qkv16 + 2 * QKV;
    const float SC = 0.125f * 1.4426950408889634f;

    // 1) convert all inputs in one launch
    prep_all_kernel<<<dim3(256, 5), 256>>>(x, Wq, Wk, Wv, Wo, x16, wh16);

    // 2) q,k,v projections (q scaled by SC)
    gemm_w<128><<<dim3(E_ / 128, NTOK / 128, 3), 256, SMEM_G>>>(
        x16, wh16, bq, bk, bv,
        nullptr, qkv16, E_, E_, E_, E_, (long long)EE, QKV, SC);

    // 3) fused attention
    attn_fused<<<dim3(S_ / AQ, B_), 512, ATT_SMEM>>>(q16, k16, v16, ctx16);

    // 4) output projection -> d_out (fp32)
    gemm_w<128><<<dim3(E_ / 128, NTOK / 128, 1), 256, SMEM_G>>>(
        ctx16, wh16 + 3 * EE, bo, nullptr, nullptr,
        out, nullptr, E_, E_, E_, E_, 0, 0, 1.0f);
}